// round 14
// baseline (speedup 1.0000x reference)
#include <cuda_runtime.h>
#include <math.h>
#include <stdint.h>

#define Dd 128
#define Hh 512
#define Ww 512
#define OD 32
#define HW (Hh*Ww)
#define INV_SQRT_2PI 0.3989422804014327f

#define NT 288
#define PCOLS 80                       // staged halo cols (72 data + 8 pad)
#define PLANE_S (72*PCOLS)             // 5760 floats = 1440 granules
#define RING_F (3*PLANE_S)             // 3-stage ring
#define SIN 76                         // s_pl padded stride
#define SMEM_DYN ((RING_F + 72*SIN) * 4)   // 69120 + 21888 = 91008 B

__device__ unsigned g_minb;
__device__ unsigned g_maxb;

__device__ __forceinline__ unsigned f2o(float f) {
    unsigned u = __float_as_uint(f);
    return (u & 0x80000000u) ? ~u : (u | 0x80000000u);
}
__device__ __forceinline__ float o2f(unsigned u) {
    return (u & 0x80000000u) ? __uint_as_float(u ^ 0x80000000u)
                             : __uint_as_float(~u);
}

// ---------------------------------------------------------------------------
// Fused z-conv + y-conv + x-conv + min/max (R10 structure, best known).
// Block = 64x64 tile x 8 z-outs.  Thread-private cp.async ring (5 granules
// per thread, no per-plane barriers).  Single retire plane buffer.
// Input loads use DEFAULT L2 policy: neighboring co-resident tiles share
// ~21% of their halo reads, and all 64 xy-tiles of a z-chunk stream the same
// planes in rough lockstep -> overlap strips should be served from L2.
// Output stores tagged L2::evict_last so k_norm's pass hits L2.
// ---------------------------------------------------------------------------
__global__ void __launch_bounds__(NT, 2) k_fused(
    const float* __restrict__ in,
    const float* __restrict__ p_mu, const float* __restrict__ p_sig,
    const float* __restrict__ p_bxy, const float* __restrict__ p_bz,
    float* __restrict__ out)
{
    extern __shared__ __align__(16) float smem[];
    float* ring = smem;                 // [3][5760]
    float* s_pl = smem + RING_F;        // [72][76]
    __shared__ float s_w[9];
    __shared__ float smin[16], smax[16];

    int t   = threadIdx.x;
    int Y0  = blockIdx.x * 64;
    int X0  = blockIdx.y * 64;
    int zo0 = blockIdx.z * 8;
    int zstart = 4 * zo0 - 3;           // input plane at iz=0 (37 planes)

    unsigned sring = (unsigned)__cvta_generic_to_shared(ring);

    uint64_t pol_l;
    asm("createpolicy.fractional.L2::evict_last.b64 %0, 1.0;"  : "=l"(pol_l));

    float bz = *p_bz, bxy = *p_bxy;
    float amp = INV_SQRT_2PI * expf(*p_mu + 0.5f * (*p_sig) * (*p_sig));
    float i2bz = 1.0f / (2.0f * bz * bz);
    float wz[9];
#pragma unroll
    for (int k = 0; k < 9; k++) {
        float d = (float)(k - 4);
        wz[k] = expf(-d * d * i2bz) * amp;
    }
    if (t < 9) {                        // xy weights to smem (reg relief)
        float d = (float)(t - 4);
        s_w[t] = expf(-d * d / (2.0f * bxy * bxy));
    }
    // s_w visible after the first retire barrier (before first use)

    float4 acc[3][5];
#pragma unroll
    for (int s = 0; s < 3; s++)
#pragma unroll
        for (int k = 0; k < 5; k++) acc[s][k] = make_float4(0.f,0.f,0.f,0.f);

    float lmin =  3.402823466e38f;
    float lmax = -3.402823466e38f;

    // stage plane P into slot P%3: 5 thread-private granules, default policy
#define ISSUE(P) do { if ((P) <= 36) {                                        \
        int z_ = zstart + (P);                                                \
        int zok_ = ((unsigned)z_ < 128u);                                     \
        const float* pz_ = in + (size_t)(zok_ ? z_ : 0) * HW;                 \
        _Pragma("unroll")                                                     \
        for (int k_ = 0; k_ < 5; k_++) {                                      \
            int g_ = t + 288 * k_;                                            \
            int r_ = g_ / 20, cs_ = g_ % 20;                                  \
            int gx_ = X0 - 4 + r_;                                            \
            int gy_ = Y0 - 4 + 4 * cs_;                                       \
            int ok_ = (zok_ && cs_ < 18 && (unsigned)gx_ < 512u &&            \
                       (unsigned)gy_ < 512u) ? 16 : 0;                        \
            int gxc_ = gx_ < 0 ? 0 : (gx_ > 511 ? 511 : gx_);                 \
            int gyc_ = gy_ < 0 ? 0 : (gy_ > 508 ? 508 : gy_);                 \
            const float* gp_ = pz_ + (size_t)gxc_ * 512 + gyc_;               \
            unsigned sa_ = sring + ((((P) % 3) * PLANE_S + 4 * g_) * 4u);     \
            asm volatile(                                                     \
                "cp.async.cg.shared.global [%0], [%1], 16, %2;"               \
                :: "r"(sa_), "l"(gp_), "r"(ok_) : "memory");                  \
        }                                                                     \
        asm volatile("cp.async.commit_group;" ::: "memory");                  \
    } } while (0)
#define WG(n) asm volatile("cp.async.wait_group " #n ";" ::: "memory")

    ISSUE(0); ISSUE(1); ISSUE(2);

    size_t outbase = (size_t)X0 * 512 + Y0;

#pragma unroll
    for (int iz = 0; iz < 37; iz++) {
        if (iz <= 34)      WG(2);
        else if (iz == 35) WG(1);
        else               WG(0);

        // my own granules -> registers (thread-private, no barrier)
        float4 v[5];
        const float4* st = reinterpret_cast<const float4*>(
            ring + (iz % 3) * PLANE_S);
#pragma unroll
        for (int k = 0; k < 5; k++) v[k] = st[t + 288 * k];

        ISSUE(iz + 3);                  // refill my slots (read already done)

        const int c = iz >> 2, q = iz & 3;      // compile-time (full unroll)

        if (c <= 7) {                           // tap kz=q for output j=c
            float wv = wz[q];
            int s = c % 3;
#pragma unroll
            for (int k = 0; k < 5; k++) {
                acc[s][k].x += wv * v[k].x; acc[s][k].y += wv * v[k].y;
                acc[s][k].z += wv * v[k].z; acc[s][k].w += wv * v[k].w;
            }
        }
        if (c >= 1 && c <= 8) {                 // tap kz=4+q for j=c-1
            float wv = wz[4 + q];
            int s = (c - 1) % 3;
#pragma unroll
            for (int k = 0; k < 5; k++) {
                acc[s][k].x += wv * v[k].x; acc[s][k].y += wv * v[k].y;
                acc[s][k].z += wv * v[k].z; acc[s][k].w += wv * v[k].w;
            }
        }
        if (q == 0 && c >= 2) {                 // tap kz=8, then RETIRE j=c-2
            const int jout = c - 2;             // 0..7
            const int s = jout % 3;
            float wv = wz[8];
#pragma unroll
            for (int k = 0; k < 5; k++) {
                acc[s][k].x += wv * v[k].x; acc[s][k].y += wv * v[k].y;
                acc[s][k].z += wv * v[k].z; acc[s][k].w += wv * v[k].w;
            }

            // ---- retire: z-convolved plane -> s_pl (float4, my granules) --
#pragma unroll
            for (int k = 0; k < 5; k++) {
                int g = t + 288 * k;
                int r = g / 20, cs = g % 20;
                if (cs < 18)
                    *reinterpret_cast<float4*>(&s_pl[r * SIN + 4 * cs]) =
                        acc[s][k];
                acc[s][k] = make_float4(0.f, 0.f, 0.f, 0.f);
            }
            __syncthreads();

            float wl[9];
#pragma unroll
            for (int k = 0; k < 9; k++) wl[k] = s_w[k];

            // ---- y-conv, in place (72 rows x 4 segs = 288 threads) ----
            {
                int row = t % 72;
                int c0  = (t / 72) * 16;
                float vy[24];
                float4* vp = reinterpret_cast<float4*>(vy);
#pragma unroll
                for (int g4 = 0; g4 < 6; g4++)
                    vp[g4] = *reinterpret_cast<float4*>(
                        &s_pl[row * SIN + c0 + 4 * g4]);
                __syncthreads();        // all reads before in-place writes
                float r_[16];
#pragma unroll
                for (int o = 0; o < 16; o++) {
                    float sv = 0.f;
#pragma unroll
                    for (int k = 0; k < 9; k++) sv += wl[k] * vy[o + k];
                    r_[o] = sv;
                }
#pragma unroll
                for (int g4 = 0; g4 < 4; g4++)
                    *reinterpret_cast<float4*>(&s_pl[row * SIN + c0 + 4 * g4]) =
                        make_float4(r_[4*g4], r_[4*g4+1], r_[4*g4+2], r_[4*g4+3]);
            }
            __syncthreads();

            // ---- x-conv + store (evict_last) + min/max ----
            if (t < 256) {
                int col = t & 63;
                int x0  = (t >> 6) * 16;
                float vx[24];
#pragma unroll
                for (int i = 0; i < 24; i++)
                    vx[i] = s_pl[(x0 + i) * SIN + col];
                float* dst = out + (size_t)(zo0 + jout) * HW + outbase
                             + (size_t)x0 * 512 + col;
#pragma unroll
                for (int o = 0; o < 16; o++) {
                    float sv = 0.f;
#pragma unroll
                    for (int k = 0; k < 9; k++) sv += wl[k] * vx[o + k];
                    asm volatile(
                        "st.global.L2::cache_hint.f32 [%0], %1, %2;"
                        :: "l"(dst + (size_t)o * 512), "f"(sv), "l"(pol_l)
                        : "memory");
                    lmin = fminf(lmin, sv);
                    lmax = fmaxf(lmax, sv);
                }
            }
            __syncthreads();            // s_pl reused by next retire
        }
    }
#undef ISSUE
#undef WG

    // ---- one block-level min/max reduction + global atomics ----
#pragma unroll
    for (int o = 16; o > 0; o >>= 1) {
        lmin = fminf(lmin, __shfl_xor_sync(0xFFFFFFFFu, lmin, o));
        lmax = fmaxf(lmax, __shfl_xor_sync(0xFFFFFFFFu, lmax, o));
    }
    if ((t & 31) == 0) { smin[t >> 5] = lmin; smax[t >> 5] = lmax; }
    __syncthreads();
    if (t < 16) {
        lmin = (t < 9) ? smin[t] :  3.402823466e38f;
        lmax = (t < 9) ? smax[t] : -3.402823466e38f;
#pragma unroll
        for (int o = 8; o > 0; o >>= 1) {
            lmin = fminf(lmin, __shfl_xor_sync(0x0000FFFFu, lmin, o));
            lmax = fmaxf(lmax, __shfl_xor_sync(0x0000FFFFu, lmax, o));
        }
        if (t == 0) {
            atomicMin(&g_minb, f2o(lmin));
            atomicMax(&g_maxb, f2o(lmax));
        }
    }
}

// ---------------------------------------------------------------------------
// Normalize: in-place min-max, 8 float4/thread, loads batched (MLP=8).
// ---------------------------------------------------------------------------
__global__ void __launch_bounds__(256) k_norm(float4* __restrict__ out)
{
    size_t base = (size_t)blockIdx.x * 2048 + threadIdx.x;
    float mn  = o2f(g_minb);
    float mx  = o2f(g_maxb);
    float inv = 1.0f / (mx - mn);

    float4 v[8];
#pragma unroll
    for (int k = 0; k < 8; k++) v[k] = out[base + 256 * k];
#pragma unroll
    for (int k = 0; k < 8; k++) {
        v[k].x = (v[k].x - mn) * inv;
        v[k].y = (v[k].y - mn) * inv;
        v[k].z = (v[k].z - mn) * inv;
        v[k].w = (v[k].w - mn) * inv;
    }
#pragma unroll
    for (int k = 0; k < 8; k++) out[base + 256 * k] = v[k];
}

extern "C" void kernel_launch(void* const* d_in, const int* in_sizes, int n_in,
                              void* d_out, int out_size)
{
    const float* inp  = (const float*)d_in[0];
    const float* mu_z = (const float*)d_in[1];
    const float* sigz = (const float*)d_in[2];
    const float* bxy  = (const float*)d_in[3];
    const float* bz   = (const float*)d_in[4];
    float* out = (float*)d_out;

    static int smem_set = 0;
    if (!smem_set) {
        cudaFuncSetAttribute(k_fused,
            cudaFuncAttributeMaxDynamicSharedMemorySize, SMEM_DYN);
        smem_set = 1;
    }

    void *pmin = nullptr, *pmax = nullptr;
    cudaGetSymbolAddress(&pmin, g_minb);
    cudaGetSymbolAddress(&pmax, g_maxb);
    cudaMemsetAsync(pmin, 0xFF, 4);
    cudaMemsetAsync(pmax, 0x00, 4);

    dim3 g(Ww / 64, Hh / 64, OD / 8);   // (8, 8, 4) = 256 blocks
    k_fused<<<g, NT, SMEM_DYN>>>(inp, mu_z, sigz, bxy, bz, out);

    int n4 = OD * HW / 4;               // 2,097,152 float4s
    k_norm<<<n4 / 2048, 256>>>((float4*)out);
}

// round 15
// speedup vs baseline: 1.0365x; 1.0365x over previous
#include <cuda_runtime.h>
#include <math.h>
#include <stdint.h>

#define Dd 128
#define Hh 512
#define Ww 512
#define OD 32
#define HW (Hh*Ww)
#define INV_SQRT_2PI 0.3989422804014327f

#define NT 288
#define PCOLS 80                       // staged halo cols (72 data + 8 pad)
#define PLANE_S (72*PCOLS)             // 5760 floats = 1440 granules
#define RING_F (3*PLANE_S)             // 3-stage ring
#define SIN 76                         // s_pl padded stride
#define SMEM_DYN ((RING_F + 72*SIN) * 4)   // 69120 + 21888 = 91008 B

__device__ unsigned g_minb;
__device__ unsigned g_maxb;

__device__ __forceinline__ unsigned f2o(float f) {
    unsigned u = __float_as_uint(f);
    return (u & 0x80000000u) ? ~u : (u | 0x80000000u);
}
__device__ __forceinline__ float o2f(unsigned u) {
    return (u & 0x80000000u) ? __uint_as_float(u ^ 0x80000000u)
                             : __uint_as_float(~u);
}

// ---------------------------------------------------------------------------
// Fused z-conv + y-conv + x-conv + min/max (R10 configuration — measured
// best: input cp.async tagged L2::evict_first, output stores evict_last).
// Block = 64x64 tile x 8 z-outs.  Thread-private cp.async ring (5 granules
// per thread, no per-plane barriers).  Single retire plane buffer.
// Prologue loads are issued BEFORE the expf weight chain so the first 3
// plane-fetches overlap the MUFU-bound prologue.
// ---------------------------------------------------------------------------
__global__ void __launch_bounds__(NT, 2) k_fused(
    const float* __restrict__ in,
    const float* __restrict__ p_mu, const float* __restrict__ p_sig,
    const float* __restrict__ p_bxy, const float* __restrict__ p_bz,
    float* __restrict__ out)
{
    extern __shared__ __align__(16) float smem[];
    float* ring = smem;                 // [3][5760]
    float* s_pl = smem + RING_F;        // [72][76]
    __shared__ float s_w[9];
    __shared__ float smin[16], smax[16];

    int t   = threadIdx.x;
    int Y0  = blockIdx.x * 64;
    int X0  = blockIdx.y * 64;
    int zo0 = blockIdx.z * 8;
    int zstart = 4 * zo0 - 3;           // input plane at iz=0 (37 planes)

    unsigned sring = (unsigned)__cvta_generic_to_shared(ring);

    uint64_t pol_f, pol_l;
    asm("createpolicy.fractional.L2::evict_first.b64 %0, 1.0;" : "=l"(pol_f));
    asm("createpolicy.fractional.L2::evict_last.b64 %0, 1.0;"  : "=l"(pol_l));

    // stage plane P into slot P%3: 5 thread-private granules (evict_first)
#define ISSUE(P) do { if ((P) <= 36) {                                        \
        int z_ = zstart + (P);                                                \
        int zok_ = ((unsigned)z_ < 128u);                                     \
        const float* pz_ = in + (size_t)(zok_ ? z_ : 0) * HW;                 \
        _Pragma("unroll")                                                     \
        for (int k_ = 0; k_ < 5; k_++) {                                      \
            int g_ = t + 288 * k_;                                            \
            int r_ = g_ / 20, cs_ = g_ % 20;                                  \
            int gx_ = X0 - 4 + r_;                                            \
            int gy_ = Y0 - 4 + 4 * cs_;                                       \
            int ok_ = (zok_ && cs_ < 18 && (unsigned)gx_ < 512u &&            \
                       (unsigned)gy_ < 512u) ? 16 : 0;                        \
            int gxc_ = gx_ < 0 ? 0 : (gx_ > 511 ? 511 : gx_);                 \
            int gyc_ = gy_ < 0 ? 0 : (gy_ > 508 ? 508 : gy_);                 \
            const float* gp_ = pz_ + (size_t)gxc_ * 512 + gyc_;               \
            unsigned sa_ = sring + ((((P) % 3) * PLANE_S + 4 * g_) * 4u);     \
            asm volatile(                                                     \
                "cp.async.cg.shared.global.L2::cache_hint "                   \
                "[%0], [%1], 16, %2, %3;"                                     \
                :: "r"(sa_), "l"(gp_), "r"(ok_), "l"(pol_f) : "memory");      \
        }                                                                     \
        asm volatile("cp.async.commit_group;" ::: "memory");                  \
    } } while (0)
#define WG(n) asm volatile("cp.async.wait_group " #n ";" ::: "memory")

    // prologue loads FIRST — overlap the expf chain below with DRAM latency
    ISSUE(0); ISSUE(1); ISSUE(2);

    float bz = *p_bz, bxy = *p_bxy;
    float amp = INV_SQRT_2PI * expf(*p_mu + 0.5f * (*p_sig) * (*p_sig));
    float i2bz = 1.0f / (2.0f * bz * bz);
    float wz[9];
#pragma unroll
    for (int k = 0; k < 9; k++) {
        float d = (float)(k - 4);
        wz[k] = expf(-d * d * i2bz) * amp;
    }
    if (t < 9) {                        // xy weights to smem (reg relief)
        float d = (float)(t - 4);
        s_w[t] = expf(-d * d / (2.0f * bxy * bxy));
    }
    // s_w visible after the first retire barrier (before first use)

    float4 acc[3][5];
#pragma unroll
    for (int s = 0; s < 3; s++)
#pragma unroll
        for (int k = 0; k < 5; k++) acc[s][k] = make_float4(0.f,0.f,0.f,0.f);

    float lmin =  3.402823466e38f;
    float lmax = -3.402823466e38f;

    size_t outbase = (size_t)X0 * 512 + Y0;

#pragma unroll
    for (int iz = 0; iz < 37; iz++) {
        if (iz <= 34)      WG(2);
        else if (iz == 35) WG(1);
        else               WG(0);

        // my own granules -> registers (thread-private, no barrier)
        float4 v[5];
        const float4* st = reinterpret_cast<const float4*>(
            ring + (iz % 3) * PLANE_S);
#pragma unroll
        for (int k = 0; k < 5; k++) v[k] = st[t + 288 * k];

        ISSUE(iz + 3);                  // refill my slots (read already done)

        const int c = iz >> 2, q = iz & 3;      // compile-time (full unroll)

        if (c <= 7) {                           // tap kz=q for output j=c
            float wv = wz[q];
            int s = c % 3;
#pragma unroll
            for (int k = 0; k < 5; k++) {
                acc[s][k].x += wv * v[k].x; acc[s][k].y += wv * v[k].y;
                acc[s][k].z += wv * v[k].z; acc[s][k].w += wv * v[k].w;
            }
        }
        if (c >= 1 && c <= 8) {                 // tap kz=4+q for j=c-1
            float wv = wz[4 + q];
            int s = (c - 1) % 3;
#pragma unroll
            for (int k = 0; k < 5; k++) {
                acc[s][k].x += wv * v[k].x; acc[s][k].y += wv * v[k].y;
                acc[s][k].z += wv * v[k].z; acc[s][k].w += wv * v[k].w;
            }
        }
        if (q == 0 && c >= 2) {                 // tap kz=8, then RETIRE j=c-2
            const int jout = c - 2;             // 0..7
            const int s = jout % 3;
            float wv = wz[8];
#pragma unroll
            for (int k = 0; k < 5; k++) {
                acc[s][k].x += wv * v[k].x; acc[s][k].y += wv * v[k].y;
                acc[s][k].z += wv * v[k].z; acc[s][k].w += wv * v[k].w;
            }

            // ---- retire: z-convolved plane -> s_pl (float4, my granules) --
#pragma unroll
            for (int k = 0; k < 5; k++) {
                int g = t + 288 * k;
                int r = g / 20, cs = g % 20;
                if (cs < 18)
                    *reinterpret_cast<float4*>(&s_pl[r * SIN + 4 * cs]) =
                        acc[s][k];
                acc[s][k] = make_float4(0.f, 0.f, 0.f, 0.f);
            }
            __syncthreads();

            float wl[9];
#pragma unroll
            for (int k = 0; k < 9; k++) wl[k] = s_w[k];

            // ---- y-conv, in place (72 rows x 4 segs = 288 threads) ----
            {
                int row = t % 72;
                int c0  = (t / 72) * 16;
                float vy[24];
                float4* vp = reinterpret_cast<float4*>(vy);
#pragma unroll
                for (int g4 = 0; g4 < 6; g4++)
                    vp[g4] = *reinterpret_cast<float4*>(
                        &s_pl[row * SIN + c0 + 4 * g4]);
                __syncthreads();        // all reads before in-place writes
                float r_[16];
#pragma unroll
                for (int o = 0; o < 16; o++) {
                    float sv = 0.f;
#pragma unroll
                    for (int k = 0; k < 9; k++) sv += wl[k] * vy[o + k];
                    r_[o] = sv;
                }
#pragma unroll
                for (int g4 = 0; g4 < 4; g4++)
                    *reinterpret_cast<float4*>(&s_pl[row * SIN + c0 + 4 * g4]) =
                        make_float4(r_[4*g4], r_[4*g4+1], r_[4*g4+2], r_[4*g4+3]);
            }
            __syncthreads();

            // ---- x-conv + store (evict_last) + min/max ----
            if (t < 256) {
                int col = t & 63;
                int x0  = (t >> 6) * 16;
                float vx[24];
#pragma unroll
                for (int i = 0; i < 24; i++)
                    vx[i] = s_pl[(x0 + i) * SIN + col];
                float* dst = out + (size_t)(zo0 + jout) * HW + outbase
                             + (size_t)x0 * 512 + col;
#pragma unroll
                for (int o = 0; o < 16; o++) {
                    float sv = 0.f;
#pragma unroll
                    for (int k = 0; k < 9; k++) sv += wl[k] * vx[o + k];
                    asm volatile(
                        "st.global.L2::cache_hint.f32 [%0], %1, %2;"
                        :: "l"(dst + (size_t)o * 512), "f"(sv), "l"(pol_l)
                        : "memory");
                    lmin = fminf(lmin, sv);
                    lmax = fmaxf(lmax, sv);
                }
            }
            __syncthreads();            // s_pl reused by next retire
        }
    }
#undef ISSUE
#undef WG

    // ---- one block-level min/max reduction + global atomics ----
#pragma unroll
    for (int o = 16; o > 0; o >>= 1) {
        lmin = fminf(lmin, __shfl_xor_sync(0xFFFFFFFFu, lmin, o));
        lmax = fmaxf(lmax, __shfl_xor_sync(0xFFFFFFFFu, lmax, o));
    }
    if ((t & 31) == 0) { smin[t >> 5] = lmin; smax[t >> 5] = lmax; }
    __syncthreads();
    if (t < 16) {
        lmin = (t < 9) ? smin[t] :  3.402823466e38f;
        lmax = (t < 9) ? smax[t] : -3.402823466e38f;
#pragma unroll
        for (int o = 8; o > 0; o >>= 1) {
            lmin = fminf(lmin, __shfl_xor_sync(0x0000FFFFu, lmin, o));
            lmax = fmaxf(lmax, __shfl_xor_sync(0x0000FFFFu, lmax, o));
        }
        if (t == 0) {
            atomicMin(&g_minb, f2o(lmin));
            atomicMax(&g_maxb, f2o(lmax));
        }
    }
}

// ---------------------------------------------------------------------------
// Normalize: in-place min-max on d_out, 4 float4 per thread (R10 config).
// ---------------------------------------------------------------------------
__global__ void __launch_bounds__(256) k_norm(float4* __restrict__ out)
{
    int i = blockIdx.x * 1024 + threadIdx.x;
    float mn = o2f(g_minb);
    float mx = o2f(g_maxb);
    float inv = 1.0f / (mx - mn);
    float4 a = out[i];
    float4 b = out[i + 256];
    float4 cc = out[i + 512];
    float4 d = out[i + 768];
    a.x=(a.x-mn)*inv; a.y=(a.y-mn)*inv; a.z=(a.z-mn)*inv; a.w=(a.w-mn)*inv;
    b.x=(b.x-mn)*inv; b.y=(b.y-mn)*inv; b.z=(b.z-mn)*inv; b.w=(b.w-mn)*inv;
    cc.x=(cc.x-mn)*inv; cc.y=(cc.y-mn)*inv; cc.z=(cc.z-mn)*inv; cc.w=(cc.w-mn)*inv;
    d.x=(d.x-mn)*inv; d.y=(d.y-mn)*inv; d.z=(d.z-mn)*inv; d.w=(d.w-mn)*inv;
    out[i] = a;
    out[i + 256] = b;
    out[i + 512] = cc;
    out[i + 768] = d;
}

extern "C" void kernel_launch(void* const* d_in, const int* in_sizes, int n_in,
                              void* d_out, int out_size)
{
    const float* inp  = (const float*)d_in[0];
    const float* mu_z = (const float*)d_in[1];
    const float* sigz = (const float*)d_in[2];
    const float* bxy  = (const float*)d_in[3];
    const float* bz   = (const float*)d_in[4];
    float* out = (float*)d_out;

    static int smem_set = 0;
    if (!smem_set) {
        cudaFuncSetAttribute(k_fused,
            cudaFuncAttributeMaxDynamicSharedMemorySize, SMEM_DYN);
        smem_set = 1;
    }

    void *pmin = nullptr, *pmax = nullptr;
    cudaGetSymbolAddress(&pmin, g_minb);
    cudaGetSymbolAddress(&pmax, g_maxb);
    cudaMemsetAsync(pmin, 0xFF, 4);
    cudaMemsetAsync(pmax, 0x00, 4);

    dim3 g(Ww / 64, Hh / 64, OD / 8);   // (8, 8, 4) = 256 blocks
    k_fused<<<g, NT, SMEM_DYN>>>(inp, mu_z, sigz, bxy, bz, out);

    int n4 = OD * HW / 4;               // 2,097,152 float4s
    k_norm<<<n4 / 1024, 256>>>((float4*)out);
}

// round 16
// speedup vs baseline: 1.0646x; 1.0271x over previous
#include <cuda_runtime.h>
#include <math.h>
#include <stdint.h>

#define Dd 128
#define Hh 512
#define Ww 512
#define OD 32
#define HW (Hh*Ww)
#define INV_SQRT_2PI 0.3989422804014327f

#define NT 288
#define PCOLS 80                       // staged halo cols (72 data + 8 pad)
#define PLANE_S (72*PCOLS)             // 5760 floats = 1440 granules
#define RING_F (3*PLANE_S)             // 3-stage ring
#define SIN 76                         // s_pl padded stride
#define SMEM_DYN ((RING_F + 72*SIN) * 4)   // 69120 + 21888 = 91008 B

__device__ unsigned g_minb;
__device__ unsigned g_maxb;

__device__ __forceinline__ unsigned f2o(float f) {
    unsigned u = __float_as_uint(f);
    return (u & 0x80000000u) ? ~u : (u | 0x80000000u);
}
__device__ __forceinline__ float o2f(unsigned u) {
    return (u & 0x80000000u) ? __uint_as_float(u ^ 0x80000000u)
                             : __uint_as_float(~u);
}

// ---------------------------------------------------------------------------
// Fused z-conv + y-conv + x-conv + min/max.  Block = 64x64 tile x 8 z-outs.
// THREAD-PRIVATE cp.async ring: halo padded to 72x80 -> 1440 granules = 5 per
// thread; each thread stages and consumes ITS OWN granules, so the only ring
// ordering needed is cp.async.wait_group (no per-plane __syncthreads).
// Granules are 4-aligned and image bounds are multiples of 4, so every
// granule is fully valid or fully zero-filled.  Every 4th plane retires one
// z-convolved 72x72 plane through smem -> in-place y-conv -> x-conv -> store.
// (Byte-exact R10 configuration — best measured: 51.2us.)
// ---------------------------------------------------------------------------
__global__ void __launch_bounds__(NT, 2) k_fused(
    const float* __restrict__ in,
    const float* __restrict__ p_mu, const float* __restrict__ p_sig,
    const float* __restrict__ p_bxy, const float* __restrict__ p_bz,
    float* __restrict__ out)
{
    extern __shared__ __align__(16) float smem[];
    float* ring = smem;                 // [3][5760]
    float* s_pl = smem + RING_F;        // [72][76]
    __shared__ float s_w[9];
    __shared__ float smin[16], smax[16];

    int t   = threadIdx.x;
    int Y0  = blockIdx.x * 64;
    int X0  = blockIdx.y * 64;
    int zo0 = blockIdx.z * 8;
    int zstart = 4 * zo0 - 3;           // input plane at iz=0 (37 planes)

    unsigned sring = (unsigned)__cvta_generic_to_shared(ring);

    uint64_t pol_f;
    asm("createpolicy.fractional.L2::evict_first.b64 %0, 1.0;" : "=l"(pol_f));

    float bz = *p_bz, bxy = *p_bxy;
    float amp = INV_SQRT_2PI * expf(*p_mu + 0.5f * (*p_sig) * (*p_sig));
    float i2bz = 1.0f / (2.0f * bz * bz);
    float wz[9];
#pragma unroll
    for (int k = 0; k < 9; k++) {
        float d = (float)(k - 4);
        wz[k] = expf(-d * d * i2bz) * amp;
    }
    if (t < 9) {                        // xy weights to smem (reg relief)
        float d = (float)(t - 4);
        s_w[t] = expf(-d * d / (2.0f * bxy * bxy));
    }
    // s_w visible after the first retire barrier (before first use)

    float4 acc[3][5];
#pragma unroll
    for (int s = 0; s < 3; s++)
#pragma unroll
        for (int k = 0; k < 5; k++) acc[s][k] = make_float4(0.f,0.f,0.f,0.f);

    float lmin =  3.402823466e38f;
    float lmax = -3.402823466e38f;

    // stage plane P into slot P%3: 5 thread-private granules
#define ISSUE(P) do { if ((P) <= 36) {                                        \
        int z_ = zstart + (P);                                                \
        int zok_ = ((unsigned)z_ < 128u);                                     \
        const float* pz_ = in + (size_t)(zok_ ? z_ : 0) * HW;                 \
        _Pragma("unroll")                                                     \
        for (int k_ = 0; k_ < 5; k_++) {                                      \
            int g_ = t + 288 * k_;                                            \
            int r_ = g_ / 20, cs_ = g_ % 20;                                  \
            int gx_ = X0 - 4 + r_;                                            \
            int gy_ = Y0 - 4 + 4 * cs_;                                       \
            int ok_ = (zok_ && cs_ < 18 && (unsigned)gx_ < 512u &&            \
                       (unsigned)gy_ < 512u) ? 16 : 0;                        \
            int gxc_ = gx_ < 0 ? 0 : (gx_ > 511 ? 511 : gx_);                 \
            int gyc_ = gy_ < 0 ? 0 : (gy_ > 508 ? 508 : gy_);                 \
            const float* gp_ = pz_ + (size_t)gxc_ * 512 + gyc_;               \
            unsigned sa_ = sring + ((((P) % 3) * PLANE_S + 4 * g_) * 4u);     \
            asm volatile(                                                     \
                "cp.async.cg.shared.global.L2::cache_hint "                   \
                "[%0], [%1], 16, %2, %3;"                                     \
                :: "r"(sa_), "l"(gp_), "r"(ok_), "l"(pol_f) : "memory");      \
        }                                                                     \
        asm volatile("cp.async.commit_group;" ::: "memory");                  \
    } } while (0)
#define WG(n) asm volatile("cp.async.wait_group " #n ";" ::: "memory")

    ISSUE(0); ISSUE(1); ISSUE(2);

    size_t outbase = (size_t)X0 * 512 + Y0;

#pragma unroll
    for (int iz = 0; iz < 37; iz++) {
        if (iz <= 34)      WG(2);
        else if (iz == 35) WG(1);
        else               WG(0);

        // my own granules -> registers (thread-private, no barrier)
        float4 v[5];
        const float4* st = reinterpret_cast<const float4*>(
            ring + (iz % 3) * PLANE_S);
#pragma unroll
        for (int k = 0; k < 5; k++) v[k] = st[t + 288 * k];

        ISSUE(iz + 3);                  // refill my slots (read already done)

        const int c = iz >> 2, q = iz & 3;      // compile-time (full unroll)

        if (c <= 7) {                           // tap kz=q for output j=c
            float wv = wz[q];
            int s = c % 3;
#pragma unroll
            for (int k = 0; k < 5; k++) {
                acc[s][k].x += wv * v[k].x; acc[s][k].y += wv * v[k].y;
                acc[s][k].z += wv * v[k].z; acc[s][k].w += wv * v[k].w;
            }
        }
        if (c >= 1 && c <= 8) {                 // tap kz=4+q for j=c-1
            float wv = wz[4 + q];
            int s = (c - 1) % 3;
#pragma unroll
            for (int k = 0; k < 5; k++) {
                acc[s][k].x += wv * v[k].x; acc[s][k].y += wv * v[k].y;
                acc[s][k].z += wv * v[k].z; acc[s][k].w += wv * v[k].w;
            }
        }
        if (q == 0 && c >= 2) {                 // tap kz=8, then RETIRE j=c-2
            const int jout = c - 2;             // 0..7
            const int s = jout % 3;
            float wv = wz[8];
#pragma unroll
            for (int k = 0; k < 5; k++) {
                acc[s][k].x += wv * v[k].x; acc[s][k].y += wv * v[k].y;
                acc[s][k].z += wv * v[k].z; acc[s][k].w += wv * v[k].w;
            }

            // ---- retire: z-convolved plane -> s_pl (float4, my granules) --
#pragma unroll
            for (int k = 0; k < 5; k++) {
                int g = t + 288 * k;
                int r = g / 20, cs = g % 20;
                if (cs < 18)
                    *reinterpret_cast<float4*>(&s_pl[r * SIN + 4 * cs]) =
                        acc[s][k];
                acc[s][k] = make_float4(0.f, 0.f, 0.f, 0.f);
            }
            __syncthreads();

            float wl[9];
#pragma unroll
            for (int k = 0; k < 9; k++) wl[k] = s_w[k];

            // ---- y-conv, in place (72 rows x 4 segs = 288 threads) ----
            {
                int row = t % 72;
                int c0  = (t / 72) * 16;
                float vy[24];
                float4* vp = reinterpret_cast<float4*>(vy);
#pragma unroll
                for (int g4 = 0; g4 < 6; g4++)
                    vp[g4] = *reinterpret_cast<float4*>(
                        &s_pl[row * SIN + c0 + 4 * g4]);
                __syncthreads();        // all reads before in-place writes
                float r_[16];
#pragma unroll
                for (int o = 0; o < 16; o++) {
                    float sv = 0.f;
#pragma unroll
                    for (int k = 0; k < 9; k++) sv += wl[k] * vy[o + k];
                    r_[o] = sv;
                }
#pragma unroll
                for (int g4 = 0; g4 < 4; g4++)
                    *reinterpret_cast<float4*>(&s_pl[row * SIN + c0 + 4 * g4]) =
                        make_float4(r_[4*g4], r_[4*g4+1], r_[4*g4+2], r_[4*g4+3]);
            }
            __syncthreads();

            // ---- x-conv + store + min/max (64 cols x 4 row-segs) ----
            if (t < 256) {
                int col = t & 63;
                int x0  = (t >> 6) * 16;
                float vx[24];
#pragma unroll
                for (int i = 0; i < 24; i++)
                    vx[i] = s_pl[(x0 + i) * SIN + col];
                float* dst = out + (size_t)(zo0 + jout) * HW + outbase
                             + (size_t)x0 * 512 + col;
#pragma unroll
                for (int o = 0; o < 16; o++) {
                    float sv = 0.f;
#pragma unroll
                    for (int k = 0; k < 9; k++) sv += wl[k] * vx[o + k];
                    dst[(size_t)o * 512] = sv;
                    lmin = fminf(lmin, sv);
                    lmax = fmaxf(lmax, sv);
                }
            }
            __syncthreads();            // s_pl reused by next retire
        }
    }
#undef ISSUE
#undef WG

    // ---- one block-level min/max reduction + global atomics ----
#pragma unroll
    for (int o = 16; o > 0; o >>= 1) {
        lmin = fminf(lmin, __shfl_xor_sync(0xFFFFFFFFu, lmin, o));
        lmax = fmaxf(lmax, __shfl_xor_sync(0xFFFFFFFFu, lmax, o));
    }
    if ((t & 31) == 0) { smin[t >> 5] = lmin; smax[t >> 5] = lmax; }
    __syncthreads();
    if (t < 16) {
        lmin = (t < 9) ? smin[t] :  3.402823466e38f;
        lmax = (t < 9) ? smax[t] : -3.402823466e38f;
#pragma unroll
        for (int o = 8; o > 0; o >>= 1) {
            lmin = fminf(lmin, __shfl_xor_sync(0x0000FFFFu, lmin, o));
            lmax = fmaxf(lmax, __shfl_xor_sync(0x0000FFFFu, lmax, o));
        }
        if (t == 0) {
            atomicMin(&g_minb, f2o(lmin));
            atomicMax(&g_maxb, f2o(lmax));
        }
    }
}

// ---------------------------------------------------------------------------
// Normalize: in-place min-max on d_out, 4 float4 per thread (more MLP).
// ---------------------------------------------------------------------------
__global__ void __launch_bounds__(256) k_norm(float4* __restrict__ out)
{
    int i = blockIdx.x * 1024 + threadIdx.x;
    float mn = o2f(g_minb);
    float mx = o2f(g_maxb);
    float inv = 1.0f / (mx - mn);
    float4 a = out[i];
    float4 b = out[i + 256];
    float4 cc = out[i + 512];
    float4 d = out[i + 768];
    a.x=(a.x-mn)*inv; a.y=(a.y-mn)*inv; a.z=(a.z-mn)*inv; a.w=(a.w-mn)*inv;
    b.x=(b.x-mn)*inv; b.y=(b.y-mn)*inv; b.z=(b.z-mn)*inv; b.w=(b.w-mn)*inv;
    cc.x=(cc.x-mn)*inv; cc.y=(cc.y-mn)*inv; cc.z=(cc.z-mn)*inv; cc.w=(cc.w-mn)*inv;
    d.x=(d.x-mn)*inv; d.y=(d.y-mn)*inv; d.z=(d.z-mn)*inv; d.w=(d.w-mn)*inv;
    out[i] = a;
    out[i + 256] = b;
    out[i + 512] = cc;
    out[i + 768] = d;
}

extern "C" void kernel_launch(void* const* d_in, const int* in_sizes, int n_in,
                              void* d_out, int out_size)
{
    const float* inp  = (const float*)d_in[0];
    const float* mu_z = (const float*)d_in[1];
    const float* sigz = (const float*)d_in[2];
    const float* bxy  = (const float*)d_in[3];
    const float* bz   = (const float*)d_in[4];
    float* out = (float*)d_out;

    static int smem_set = 0;
    if (!smem_set) {
        cudaFuncSetAttribute(k_fused,
            cudaFuncAttributeMaxDynamicSharedMemorySize, SMEM_DYN);
        smem_set = 1;
    }

    void *pmin = nullptr, *pmax = nullptr;
    cudaGetSymbolAddress(&pmin, g_minb);
    cudaGetSymbolAddress(&pmax, g_maxb);
    cudaMemsetAsync(pmin, 0xFF, 4);
    cudaMemsetAsync(pmax, 0x00, 4);

    dim3 g(Ww / 64, Hh / 64, OD / 8);   // (8, 8, 4) = 256 blocks
    k_fused<<<g, NT, SMEM_DYN>>>(inp, mu_z, sigz, bxy, bz, out);

    int n4 = OD * HW / 4;               // 2,097,152 float4s
    k_norm<<<n4 / 1024, 256>>>((float4*)out);
}

// round 17
// speedup vs baseline: 1.0813x; 1.0156x over previous
#include <cuda_runtime.h>
#include <math.h>
#include <stdint.h>

#define Dd 128
#define Hh 512
#define Ww 512
#define OD 32
#define HW (Hh*Ww)
#define INV_SQRT_2PI 0.3989422804014327f

#define NT 288
#define PCOLS 80                       // staged halo cols (72 data + 8 pad)
#define PLANE_S (72*PCOLS)             // 5760 floats = 1440 granules
#define RING_F (3*PLANE_S)             // 3-stage ring
#define SIN 76                         // s_pl padded stride
#define SMEM_DYN ((RING_F + 72*SIN) * 4)   // 69120 + 21888 = 91008 B

__device__ unsigned g_minb;
__device__ unsigned g_maxb;

__device__ __forceinline__ unsigned f2o(float f) {
    unsigned u = __float_as_uint(f);
    return (u & 0x80000000u) ? ~u : (u | 0x80000000u);
}
__device__ __forceinline__ float o2f(unsigned u) {
    return (u & 0x80000000u) ? __uint_as_float(u ^ 0x80000000u)
                             : __uint_as_float(~u);
}

// ---------------------------------------------------------------------------
// Fused z-conv + y-conv + x-conv + min/max.  Block = 64x64 tile x 8 z-outs.
// THREAD-PRIVATE cp.async ring: halo padded to 72x80 -> 1440 granules = 5 per
// thread; each thread stages and consumes ITS OWN granules, so the only ring
// ordering needed is cp.async.wait_group (no per-plane __syncthreads).
// Granules are 4-aligned and image bounds are multiples of 4, so every
// granule is fully valid or fully zero-filled.  Every 4th plane retires one
// z-convolved 72x72 plane through smem -> in-place y-conv -> x-conv -> store.
// (Champion configuration: 51.2/52.0us measured; all perturbations worse.)
// ---------------------------------------------------------------------------
__global__ void __launch_bounds__(NT, 2) k_fused(
    const float* __restrict__ in,
    const float* __restrict__ p_mu, const float* __restrict__ p_sig,
    const float* __restrict__ p_bxy, const float* __restrict__ p_bz,
    float* __restrict__ out)
{
    extern __shared__ __align__(16) float smem[];
    float* ring = smem;                 // [3][5760]
    float* s_pl = smem + RING_F;        // [72][76]
    __shared__ float s_w[9];
    __shared__ float smin[16], smax[16];

    int t   = threadIdx.x;
    int Y0  = blockIdx.x * 64;
    int X0  = blockIdx.y * 64;
    int zo0 = blockIdx.z * 8;
    int zstart = 4 * zo0 - 3;           // input plane at iz=0 (37 planes)

    unsigned sring = (unsigned)__cvta_generic_to_shared(ring);

    uint64_t pol_f;
    asm("createpolicy.fractional.L2::evict_first.b64 %0, 1.0;" : "=l"(pol_f));

    float bz = *p_bz, bxy = *p_bxy;
    float amp = INV_SQRT_2PI * expf(*p_mu + 0.5f * (*p_sig) * (*p_sig));
    float i2bz = 1.0f / (2.0f * bz * bz);
    float wz[9];
#pragma unroll
    for (int k = 0; k < 9; k++) {
        float d = (float)(k - 4);
        wz[k] = expf(-d * d * i2bz) * amp;
    }
    if (t < 9) {                        // xy weights to smem (reg relief)
        float d = (float)(t - 4);
        s_w[t] = expf(-d * d / (2.0f * bxy * bxy));
    }
    // s_w visible after the first retire barrier (before first use)

    float4 acc[3][5];
#pragma unroll
    for (int s = 0; s < 3; s++)
#pragma unroll
        for (int k = 0; k < 5; k++) acc[s][k] = make_float4(0.f,0.f,0.f,0.f);

    float lmin =  3.402823466e38f;
    float lmax = -3.402823466e38f;

    // stage plane P into slot P%3: 5 thread-private granules
#define ISSUE(P) do { if ((P) <= 36) {                                        \
        int z_ = zstart + (P);                                                \
        int zok_ = ((unsigned)z_ < 128u);                                     \
        const float* pz_ = in + (size_t)(zok_ ? z_ : 0) * HW;                 \
        _Pragma("unroll")                                                     \
        for (int k_ = 0; k_ < 5; k_++) {                                      \
            int g_ = t + 288 * k_;                                            \
            int r_ = g_ / 20, cs_ = g_ % 20;                                  \
            int gx_ = X0 - 4 + r_;                                            \
            int gy_ = Y0 - 4 + 4 * cs_;                                       \
            int ok_ = (zok_ && cs_ < 18 && (unsigned)gx_ < 512u &&            \
                       (unsigned)gy_ < 512u) ? 16 : 0;                        \
            int gxc_ = gx_ < 0 ? 0 : (gx_ > 511 ? 511 : gx_);                 \
            int gyc_ = gy_ < 0 ? 0 : (gy_ > 508 ? 508 : gy_);                 \
            const float* gp_ = pz_ + (size_t)gxc_ * 512 + gyc_;               \
            unsigned sa_ = sring + ((((P) % 3) * PLANE_S + 4 * g_) * 4u);     \
            asm volatile(                                                     \
                "cp.async.cg.shared.global.L2::cache_hint "                   \
                "[%0], [%1], 16, %2, %3;"                                     \
                :: "r"(sa_), "l"(gp_), "r"(ok_), "l"(pol_f) : "memory");      \
        }                                                                     \
        asm volatile("cp.async.commit_group;" ::: "memory");                  \
    } } while (0)
#define WG(n) asm volatile("cp.async.wait_group " #n ";" ::: "memory")

    ISSUE(0); ISSUE(1); ISSUE(2);

    size_t outbase = (size_t)X0 * 512 + Y0;

#pragma unroll
    for (int iz = 0; iz < 37; iz++) {
        if (iz <= 34)      WG(2);
        else if (iz == 35) WG(1);
        else               WG(0);

        // my own granules -> registers (thread-private, no barrier)
        float4 v[5];
        const float4* st = reinterpret_cast<const float4*>(
            ring + (iz % 3) * PLANE_S);
#pragma unroll
        for (int k = 0; k < 5; k++) v[k] = st[t + 288 * k];

        ISSUE(iz + 3);                  // refill my slots (read already done)

        const int c = iz >> 2, q = iz & 3;      // compile-time (full unroll)

        if (c <= 7) {                           // tap kz=q for output j=c
            float wv = wz[q];
            int s = c % 3;
#pragma unroll
            for (int k = 0; k < 5; k++) {
                acc[s][k].x += wv * v[k].x; acc[s][k].y += wv * v[k].y;
                acc[s][k].z += wv * v[k].z; acc[s][k].w += wv * v[k].w;
            }
        }
        if (c >= 1 && c <= 8) {                 // tap kz=4+q for j=c-1
            float wv = wz[4 + q];
            int s = (c - 1) % 3;
#pragma unroll
            for (int k = 0; k < 5; k++) {
                acc[s][k].x += wv * v[k].x; acc[s][k].y += wv * v[k].y;
                acc[s][k].z += wv * v[k].z; acc[s][k].w += wv * v[k].w;
            }
        }
        if (q == 0 && c >= 2) {                 // tap kz=8, then RETIRE j=c-2
            const int jout = c - 2;             // 0..7
            const int s = jout % 3;
            float wv = wz[8];
#pragma unroll
            for (int k = 0; k < 5; k++) {
                acc[s][k].x += wv * v[k].x; acc[s][k].y += wv * v[k].y;
                acc[s][k].z += wv * v[k].z; acc[s][k].w += wv * v[k].w;
            }

            // ---- retire: z-convolved plane -> s_pl (float4, my granules) --
#pragma unroll
            for (int k = 0; k < 5; k++) {
                int g = t + 288 * k;
                int r = g / 20, cs = g % 20;
                if (cs < 18)
                    *reinterpret_cast<float4*>(&s_pl[r * SIN + 4 * cs]) =
                        acc[s][k];
                acc[s][k] = make_float4(0.f, 0.f, 0.f, 0.f);
            }
            __syncthreads();

            float wl[9];
#pragma unroll
            for (int k = 0; k < 9; k++) wl[k] = s_w[k];

            // ---- y-conv, in place (72 rows x 4 segs = 288 threads) ----
            {
                int row = t % 72;
                int c0  = (t / 72) * 16;
                float vy[24];
                float4* vp = reinterpret_cast<float4*>(vy);
#pragma unroll
                for (int g4 = 0; g4 < 6; g4++)
                    vp[g4] = *reinterpret_cast<float4*>(
                        &s_pl[row * SIN + c0 + 4 * g4]);
                __syncthreads();        // all reads before in-place writes
                float r_[16];
#pragma unroll
                for (int o = 0; o < 16; o++) {
                    float sv = 0.f;
#pragma unroll
                    for (int k = 0; k < 9; k++) sv += wl[k] * vy[o + k];
                    r_[o] = sv;
                }
#pragma unroll
                for (int g4 = 0; g4 < 4; g4++)
                    *reinterpret_cast<float4*>(&s_pl[row * SIN + c0 + 4 * g4]) =
                        make_float4(r_[4*g4], r_[4*g4+1], r_[4*g4+2], r_[4*g4+3]);
            }
            __syncthreads();

            // ---- x-conv + store + min/max (64 cols x 4 row-segs) ----
            if (t < 256) {
                int col = t & 63;
                int x0  = (t >> 6) * 16;
                float vx[24];
#pragma unroll
                for (int i = 0; i < 24; i++)
                    vx[i] = s_pl[(x0 + i) * SIN + col];
                float* dst = out + (size_t)(zo0 + jout) * HW + outbase
                             + (size_t)x0 * 512 + col;
#pragma unroll
                for (int o = 0; o < 16; o++) {
                    float sv = 0.f;
#pragma unroll
                    for (int k = 0; k < 9; k++) sv += wl[k] * vx[o + k];
                    dst[(size_t)o * 512] = sv;
                    lmin = fminf(lmin, sv);
                    lmax = fmaxf(lmax, sv);
                }
            }
            __syncthreads();            // s_pl reused by next retire
        }
    }
#undef ISSUE
#undef WG

    // ---- one block-level min/max reduction + global atomics ----
#pragma unroll
    for (int o = 16; o > 0; o >>= 1) {
        lmin = fminf(lmin, __shfl_xor_sync(0xFFFFFFFFu, lmin, o));
        lmax = fmaxf(lmax, __shfl_xor_sync(0xFFFFFFFFu, lmax, o));
    }
    if ((t & 31) == 0) { smin[t >> 5] = lmin; smax[t >> 5] = lmax; }
    __syncthreads();
    if (t < 16) {
        lmin = (t < 9) ? smin[t] :  3.402823466e38f;
        lmax = (t < 9) ? smax[t] : -3.402823466e38f;
#pragma unroll
        for (int o = 8; o > 0; o >>= 1) {
            lmin = fminf(lmin, __shfl_xor_sync(0x0000FFFFu, lmin, o));
            lmax = fmaxf(lmax, __shfl_xor_sync(0x0000FFFFu, lmax, o));
        }
        if (t == 0) {
            atomicMin(&g_minb, f2o(lmin));
            atomicMax(&g_maxb, f2o(lmax));
        }
    }
}

// ---------------------------------------------------------------------------
// Normalize: in-place min-max on d_out, 4 float4 per thread.
// ---------------------------------------------------------------------------
__global__ void __launch_bounds__(256) k_norm(float4* __restrict__ out)
{
    int i = blockIdx.x * 1024 + threadIdx.x;
    float mn = o2f(g_minb);
    float mx = o2f(g_maxb);
    float inv = 1.0f / (mx - mn);
    float4 a = out[i];
    float4 b = out[i + 256];
    float4 cc = out[i + 512];
    float4 d = out[i + 768];
    a.x=(a.x-mn)*inv; a.y=(a.y-mn)*inv; a.z=(a.z-mn)*inv; a.w=(a.w-mn)*inv;
    b.x=(b.x-mn)*inv; b.y=(b.y-mn)*inv; b.z=(b.z-mn)*inv; b.w=(b.w-mn)*inv;
    cc.x=(cc.x-mn)*inv; cc.y=(cc.y-mn)*inv; cc.z=(cc.z-mn)*inv; cc.w=(cc.w-mn)*inv;
    d.x=(d.x-mn)*inv; d.y=(d.y-mn)*inv; d.z=(d.z-mn)*inv; d.w=(d.w-mn)*inv;
    out[i] = a;
    out[i + 256] = b;
    out[i + 512] = cc;
    out[i + 768] = d;
}

extern "C" void kernel_launch(void* const* d_in, const int* in_sizes, int n_in,
                              void* d_out, int out_size)
{
    const float* inp  = (const float*)d_in[0];
    const float* mu_z = (const float*)d_in[1];
    const float* sigz = (const float*)d_in[2];
    const float* bxy  = (const float*)d_in[3];
    const float* bz   = (const float*)d_in[4];
    float* out = (float*)d_out;

    static int smem_set = 0;
    if (!smem_set) {
        cudaFuncSetAttribute(k_fused,
            cudaFuncAttributeMaxDynamicSharedMemorySize, SMEM_DYN);
        smem_set = 1;
    }

    void *pmin = nullptr, *pmax = nullptr;
    cudaGetSymbolAddress(&pmin, g_minb);
    cudaGetSymbolAddress(&pmax, g_maxb);
    cudaMemsetAsync(pmin, 0xFF, 4);
    cudaMemsetAsync(pmax, 0x00, 4);

    dim3 g(Ww / 64, Hh / 64, OD / 8);   // (8, 8, 4) = 256 blocks
    k_fused<<<g, NT, SMEM_DYN>>>(inp, mu_z, sigz, bxy, bz, out);

    int n4 = OD * HW / 4;               // 2,097,152 float4s
    k_norm<<<n4 / 1024, 256>>>((float4*)out);
}